// round 8
// baseline (speedup 1.0000x reference)
#include <cuda_runtime.h>
#include <cstdint>

#define NN 100000
#define NE 1600000
#define HD 64
#define IND 5
#define OUTD 4
#define BN_EPS 1e-5f
#define TS 65   // padded tile row stride (floats)
#define SCAN_NBLK 98   // cdiv(100000, 1024)

// ---------------- scratch (static; no allocation allowed) ----------------
__device__ float  g_xw[(size_t)NN * HD];
__device__ float  g_agg[(size_t)NN * HD];
__device__ int    g_cnt_s[NN], g_cnt_t[NN];
__device__ int    g_start_s[NN], g_start_t[NN];
__device__ int    g_cur_s[NN],  g_cur_t[NN];
__device__ float  g_dv_s[NN],  g_dv_t[NN];
__device__ int2   g_adj_s[NE], g_adj_t[NE];      // (row, norm-bits), grouped by col
__device__ int    g_bsum[256];                   // [2][128] block sums for scan
__device__ double g_sum[HD], g_sumsq[HD];
__device__ float  g_a[HD], g_c[HD];              // BN scale/shift

static inline int cdiv(long long a, int b) { return (int)((a + b - 1) / b); }

// ---------------- CSR build ----------------
__global__ void zero_cnt_kernel(int* a, int* b, int n) {
    int i = blockIdx.x * blockDim.x + threadIdx.x;
    if (i < n) { a[i] = 0; b[i] = 0; }
}

// both graphs in one pass
__global__ void count_kernel(const int* __restrict__ s_cols, const int* __restrict__ t_cols,
                             int* __restrict__ cnt_s, int* __restrict__ cnt_t, int nE) {
    int e = blockIdx.x * blockDim.x + threadIdx.x;
    if (e < nE) {
        atomicAdd(&cnt_s[s_cols[e]], 1);
        atomicAdd(&cnt_t[t_cols[e]], 1);
    }
}

__global__ void dinv_kernel(const int* __restrict__ ca, const int* __restrict__ cb,
                            float* __restrict__ da, float* __restrict__ db, int n) {
    int i = blockIdx.x * blockDim.x + threadIdx.x;
    if (i < n) {
        da[i] = rsqrtf((float)ca[i] + 1.0f);
        db[i] = rsqrtf((float)cb[i] + 1.0f);
    }
}

// ---- parallel 3-phase exclusive scan ----
__global__ void scan1_kernel(const int* __restrict__ cnt_s, int* __restrict__ start_s,
                             const int* __restrict__ cnt_t, int* __restrict__ start_t,
                             int* __restrict__ bsum, int n) {
    const int* cnt = blockIdx.y ? cnt_t : cnt_s;
    int* start = blockIdx.y ? start_t : start_s;
    __shared__ int sh[1024];
    int t = threadIdx.x;
    int i = blockIdx.x * 1024 + t;
    int v = (i < n) ? cnt[i] : 0;
    sh[t] = v;
    __syncthreads();
    #pragma unroll
    for (int off = 1; off < 1024; off <<= 1) {
        int x = (t >= off) ? sh[t - off] : 0;
        __syncthreads();
        sh[t] += x;
        __syncthreads();
    }
    if (i < n) start[i] = sh[t] - v;   // exclusive within block
    if (t == 1023) bsum[blockIdx.y * 128 + blockIdx.x] = sh[1023];
}

__global__ void scan2_kernel(int* __restrict__ bsum) {
    int* bs = bsum + blockIdx.x * 128;
    __shared__ int sh[128];
    int t = threadIdx.x;
    int v = (t < SCAN_NBLK) ? bs[t] : 0;
    sh[t] = v;
    __syncthreads();
    #pragma unroll
    for (int off = 1; off < 128; off <<= 1) {
        int x = (t >= off) ? sh[t - off] : 0;
        __syncthreads();
        sh[t] += x;
        __syncthreads();
    }
    bs[t] = sh[t] - v;   // exclusive
}

__global__ void scan3_kernel(int* __restrict__ start_s, int* __restrict__ cur_s,
                             int* __restrict__ start_t, int* __restrict__ cur_t,
                             const int* __restrict__ bsum, int n) {
    int g = blockIdx.y;
    int* start = g ? start_t : start_s;
    int* cur   = g ? cur_t   : cur_s;
    int i = blockIdx.x * blockDim.x + threadIdx.x;
    if (i < n) {
        int v = start[i] + bsum[g * 128 + (i >> 10)];
        start[i] = v;
        cur[i] = v;
    }
}

// both graphs in one pass
__global__ void place_kernel(const int* __restrict__ s_rows, const int* __restrict__ s_cols,
                             const int* __restrict__ t_rows, const int* __restrict__ t_cols,
                             const float* __restrict__ dv_s, const float* __restrict__ dv_t,
                             int* __restrict__ cur_s, int* __restrict__ cur_t,
                             int2* __restrict__ adj_s, int2* __restrict__ adj_t, int nE) {
    int e = blockIdx.x * blockDim.x + threadIdx.x;
    if (e >= nE) return;
    {
        int r = s_rows[e], c = s_cols[e];
        int pos = atomicAdd(&cur_s[c], 1);
        adj_s[pos] = make_int2(r, __float_as_int(dv_s[r] * dv_s[c]));
    }
    {
        int r = t_rows[e], c = t_cols[e];
        int pos = atomicAdd(&cur_t[c], 1);
        adj_t[pos] = make_int2(r, __float_as_int(dv_t[r] * dv_t[c]));
    }
}

// ---------------- layer 1 projection: xw = x(Nx5) @ w1(5x64) ----------------
__global__ void xw1_kernel(const float* __restrict__ x, const float* __restrict__ w,
                           float* __restrict__ out, int n) {
    __shared__ float Ws[IND * HD];
    int t = threadIdx.x;
    for (int i = t; i < IND * HD; i += blockDim.x) Ws[i] = w[i];
    __syncthreads();
    int idx = blockIdx.x * blockDim.x + t;
    int node = idx >> 4, q = idx & 15;
    if (node >= n) return;
    float xr[IND];
    #pragma unroll
    for (int k = 0; k < IND; k++) xr[k] = __ldg(&x[(size_t)node * IND + k]);
    float4 a = make_float4(0.f, 0.f, 0.f, 0.f);
    #pragma unroll
    for (int k = 0; k < IND; k++) {
        const float* wr = &Ws[k * HD + q * 4];
        a.x = fmaf(xr[k], wr[0], a.x);
        a.y = fmaf(xr[k], wr[1], a.y);
        a.z = fmaf(xr[k], wr[2], a.z);
        a.w = fmaf(xr[k], wr[3], a.w);
    }
    ((float4*)out)[(size_t)node * 16 + q] = a;
}

// ---------------- aggregation (gather over CSR), software-pipelined ----------------
// agg[c] = b + dinv[c]^2 * xw[c] + sum_{edges into c} norm * xw[row]
// 16 lanes per node. The adj loads for group i+1 are issued before the xw
// loads of group i are consumed, hiding the adj->xw dependent-latency chain.
__global__ void __launch_bounds__(256)
gather_kernel(const int2* __restrict__ adj, const int* __restrict__ start,
              const int* __restrict__ cnt, const float* __restrict__ dinv,
              const float* __restrict__ xw, const float* __restrict__ bias,
              float* __restrict__ agg, int n) {
    int t = threadIdx.x;
    if (blockIdx.x == 0 && t < HD) { g_sum[t] = 0.0; g_sumsq[t] = 0.0; }
    int idx = blockIdx.x * 256 + t;
    int node = idx >> 4, q = idx & 15;
    if (node >= n) return;

    const float4* xw4 = (const float4*)xw;
    float4 acc = __ldg(&((const float4*)bias)[q]);
    float s = dinv[node]; s *= s;
    float4 self = __ldg(&xw4[(size_t)node * 16 + q]);
    acc.x = fmaf(s, self.x, acc.x);
    acc.y = fmaf(s, self.y, acc.y);
    acc.z = fmaf(s, self.z, acc.z);
    acc.w = fmaf(s, self.w, acc.w);

    int p  = start[node];
    int p1 = p + cnt[node];

    if (p + 4 <= p1) {
        // prologue: first adj group
        int2 a0 = __ldg(&adj[p]);
        int2 a1 = __ldg(&adj[p + 1]);
        int2 a2 = __ldg(&adj[p + 2]);
        int2 a3 = __ldg(&adj[p + 3]);
        p += 4;
        while (p + 4 <= p1) {
            // prefetch next adj group (overlaps with current xw loads below)
            int2 b0 = __ldg(&adj[p]);
            int2 b1 = __ldg(&adj[p + 1]);
            int2 b2 = __ldg(&adj[p + 2]);
            int2 b3 = __ldg(&adj[p + 3]);
            float4 v0 = __ldg(&xw4[(size_t)a0.x * 16 + q]);
            float4 v1 = __ldg(&xw4[(size_t)a1.x * 16 + q]);
            float4 v2 = __ldg(&xw4[(size_t)a2.x * 16 + q]);
            float4 v3 = __ldg(&xw4[(size_t)a3.x * 16 + q]);
            float w0 = __int_as_float(a0.y), w1 = __int_as_float(a1.y);
            float w2 = __int_as_float(a2.y), w3 = __int_as_float(a3.y);
            acc.x = fmaf(w3, v3.x, fmaf(w2, v2.x, fmaf(w1, v1.x, fmaf(w0, v0.x, acc.x))));
            acc.y = fmaf(w3, v3.y, fmaf(w2, v2.y, fmaf(w1, v1.y, fmaf(w0, v0.y, acc.y))));
            acc.z = fmaf(w3, v3.z, fmaf(w2, v2.z, fmaf(w1, v1.z, fmaf(w0, v0.z, acc.z))));
            acc.w = fmaf(w3, v3.w, fmaf(w2, v2.w, fmaf(w1, v1.w, fmaf(w0, v0.w, acc.w))));
            a0 = b0; a1 = b1; a2 = b2; a3 = b3;
            p += 4;
        }
        // epilogue: drain last prefetched group
        {
            float4 v0 = __ldg(&xw4[(size_t)a0.x * 16 + q]);
            float4 v1 = __ldg(&xw4[(size_t)a1.x * 16 + q]);
            float4 v2 = __ldg(&xw4[(size_t)a2.x * 16 + q]);
            float4 v3 = __ldg(&xw4[(size_t)a3.x * 16 + q]);
            float w0 = __int_as_float(a0.y), w1 = __int_as_float(a1.y);
            float w2 = __int_as_float(a2.y), w3 = __int_as_float(a3.y);
            acc.x = fmaf(w3, v3.x, fmaf(w2, v2.x, fmaf(w1, v1.x, fmaf(w0, v0.x, acc.x))));
            acc.y = fmaf(w3, v3.y, fmaf(w2, v2.y, fmaf(w1, v1.y, fmaf(w0, v0.y, acc.y))));
            acc.z = fmaf(w3, v3.z, fmaf(w2, v2.z, fmaf(w1, v1.z, fmaf(w0, v0.z, acc.z))));
            acc.w = fmaf(w3, v3.w, fmaf(w2, v2.w, fmaf(w1, v1.w, fmaf(w0, v0.w, acc.w))));
        }
    }
    // remainder (deg % 4)
    for (; p < p1; p++) {
        int2 a = __ldg(&adj[p]);
        float w = __int_as_float(a.y);
        float4 v = __ldg(&xw4[(size_t)a.x * 16 + q]);
        acc.x = fmaf(w, v.x, acc.x);
        acc.y = fmaf(w, v.y, acc.y);
        acc.z = fmaf(w, v.z, acc.z);
        acc.w = fmaf(w, v.w, acc.w);
    }
    ((float4*)agg)[(size_t)node * 16 + q] = acc;
}

// ---------------- BN stats: column sums / sumsq ----------------
__global__ void bn_stats_kernel(const float* __restrict__ agg, int n) {
    int t = threadIdx.x;              // 256
    int col = t & 63, sub = t >> 6;   // 4 sub-rows
    float s = 0.f, s2 = 0.f;
    for (int i = blockIdx.x * 4 + sub; i < n; i += gridDim.x * 4) {
        float v = agg[(size_t)i * HD + col];
        s += v;
        s2 = fmaf(v, v, s2);
    }
    __shared__ float sh0[256], sh1[256];
    sh0[t] = s; sh1[t] = s2;
    __syncthreads();
    if (sub == 0) {
        double ds  = (double)sh0[t] + sh0[t + 64] + sh0[t + 128] + sh0[t + 192];
        double ds2 = (double)sh1[t] + sh1[t + 64] + sh1[t + 128] + sh1[t + 192];
        atomicAdd(&g_sum[col], ds);
        atomicAdd(&g_sumsq[col], ds2);
    }
}

__global__ void bn_finalize_kernel(const float* __restrict__ g, const float* __restrict__ be, int n) {
    int t = threadIdx.x;
    if (t >= HD) return;
    double mean = g_sum[t] / n;
    double var  = g_sumsq[t] / n - mean * mean;
    float a = g[t] * rsqrtf((float)var + BN_EPS);
    g_a[t] = a;
    g_c[t] = be[t] - (float)mean * a;
}

// ---------------- fused BN+ReLU+GEMM: xw = relu(bn(agg)) @ W ----------------
__global__ void __launch_bounds__(128)
xw_fused_kernel(const float* __restrict__ in, const float* __restrict__ W,
                float* __restrict__ out, int n) {
    __shared__ float tile[64 * TS];
    __shared__ float Ws[HD * HD];
    __shared__ float as[HD], cs[HD];
    int t = threadIdx.x;
    for (int i = t; i < HD * HD; i += 128) Ws[i] = W[i];
    if (t < HD) { as[t] = g_a[t]; cs[t] = g_c[t]; }

    int base = blockIdx.x * 64;
    int nv = min(64, n - base);
    const float4* in4 = (const float4*)(in + (size_t)base * HD);
    for (int i = t; i < nv * 16; i += 128) {
        float4 v = __ldg(&in4[i]);
        float* p = &tile[(i >> 4) * TS + (i & 15) * 4];
        p[0] = v.x; p[1] = v.y; p[2] = v.z; p[3] = v.w;
    }
    __syncthreads();

    int node = t >> 1, h = t & 1;
    bool act = (base + node) < n;
    float acc[32];
    #pragma unroll
    for (int j = 0; j < 32; j++) acc[j] = 0.f;
    if (act) {
        const float* row = &tile[node * TS];
        const float* wb  = &Ws[h * 32];
        #pragma unroll 4
        for (int k = 0; k < HD; k++) {
            float v = fmaxf(fmaf(row[k], as[k], cs[k]), 0.f);
            #pragma unroll
            for (int j = 0; j < 32; j++) acc[j] = fmaf(v, wb[k * HD + j], acc[j]);
        }
    }
    __syncthreads();
    if (act) {
        float* dst = &tile[node * TS + h * 32];
        #pragma unroll
        for (int j = 0; j < 32; j++) dst[j] = acc[j];
    }
    __syncthreads();
    float4* out4 = (float4*)(out + (size_t)base * HD);
    for (int i = t; i < nv * 16; i += 128) {
        float* p = &tile[(i >> 4) * TS + (i & 15) * 4];
        out4[i] = make_float4(p[0], p[1], p[2], p[3]);
    }
}

// ---------------- final FC: out = relu(bn(agg)) @ wfc + bfc ----------------
__global__ void __launch_bounds__(128)
fc_kernel(const float* __restrict__ agg, const float* __restrict__ wfc,
          const float* __restrict__ bfc, float* __restrict__ out, int n) {
    __shared__ float tile[128 * TS];
    __shared__ float Wf[HD * OUTD];
    __shared__ float as[HD], cs[HD];
    int t = threadIdx.x;
    if (t < HD) { as[t] = g_a[t]; cs[t] = g_c[t]; }
    if (t < HD) ((float4*)Wf)[t] = ((const float4*)wfc)[t];

    int base = blockIdx.x * 128;
    int nv = min(128, n - base);
    const float4* in4 = (const float4*)(agg + (size_t)base * HD);
    for (int i = t; i < nv * 16; i += 128) {
        float4 v = __ldg(&in4[i]);
        float* p = &tile[(i >> 4) * TS + (i & 15) * 4];
        p[0] = v.x; p[1] = v.y; p[2] = v.z; p[3] = v.w;
    }
    __syncthreads();
    if (t < nv) {
        float a0 = __ldg(&bfc[0]), a1 = __ldg(&bfc[1]);
        float a2 = __ldg(&bfc[2]), a3 = __ldg(&bfc[3]);
        const float* row = &tile[t * TS];
        #pragma unroll 8
        for (int k = 0; k < HD; k++) {
            float v = fmaxf(fmaf(row[k], as[k], cs[k]), 0.f);
            a0 = fmaf(v, Wf[k * 4 + 0], a0);
            a1 = fmaf(v, Wf[k * 4 + 1], a1);
            a2 = fmaf(v, Wf[k * 4 + 2], a2);
            a3 = fmaf(v, Wf[k * 4 + 3], a3);
        }
        ((float4*)out)[base + t] = make_float4(a0, a1, a2, a3);
    }
}

// ---------------- host orchestration ----------------
extern "C" void kernel_launch(void* const* d_in, const int* in_sizes, int n_in,
                              void* d_out, int out_size) {
    const float* x   = (const float*)d_in[0];
    const int*   sei = (const int*)d_in[1];
    const int*   tei = (const int*)d_in[2];
    const float* w1  = (const float*)d_in[3];
    const float* b1  = (const float*)d_in[4];
    const float* g1  = (const float*)d_in[5];
    const float* be1 = (const float*)d_in[6];
    const float* w2  = (const float*)d_in[7];
    const float* b2  = (const float*)d_in[8];
    const float* g2  = (const float*)d_in[9];
    const float* be2 = (const float*)d_in[10];
    const float* w3  = (const float*)d_in[11];
    const float* b3  = (const float*)d_in[12];
    const float* g3  = (const float*)d_in[13];
    const float* be3 = (const float*)d_in[14];
    const float* w4  = (const float*)d_in[15];
    const float* b4  = (const float*)d_in[16];
    const float* g4  = (const float*)d_in[17];
    const float* be4 = (const float*)d_in[18];
    const float* wfc = (const float*)d_in[19];
    const float* bfc = (const float*)d_in[20];
    float* out = (float*)d_out;

    const int n = in_sizes[0] / IND;   // 100000
    const int e = in_sizes[1] / 2;     // 1600000
    const int* s_rows = sei;  const int* s_cols = sei + e;
    const int* t_rows = tei;  const int* t_cols = tei + e;

    int *cnt_s, *cnt_t, *start_s, *start_t, *cur_s, *cur_t, *bsum;
    float *dv_s, *dv_t, *xw, *agg;
    int2 *adj_s, *adj_t;
    cudaGetSymbolAddress((void**)&cnt_s, g_cnt_s);
    cudaGetSymbolAddress((void**)&cnt_t, g_cnt_t);
    cudaGetSymbolAddress((void**)&start_s, g_start_s);
    cudaGetSymbolAddress((void**)&start_t, g_start_t);
    cudaGetSymbolAddress((void**)&cur_s, g_cur_s);
    cudaGetSymbolAddress((void**)&cur_t, g_cur_t);
    cudaGetSymbolAddress((void**)&dv_s, g_dv_s);
    cudaGetSymbolAddress((void**)&dv_t, g_dv_t);
    cudaGetSymbolAddress((void**)&xw, g_xw);
    cudaGetSymbolAddress((void**)&agg, g_agg);
    cudaGetSymbolAddress((void**)&adj_s, g_adj_s);
    cudaGetSymbolAddress((void**)&adj_t, g_adj_t);
    cudaGetSymbolAddress((void**)&bsum, g_bsum);

    const int eg = cdiv(e, 256);
    const int ng16 = cdiv((long long)n * 16, 256);

    // ---- CSR build (once per graph, reused by 2 layers each) ----
    zero_cnt_kernel<<<cdiv(n, 256), 256>>>(cnt_s, cnt_t, n);
    count_kernel<<<eg, 256>>>(s_cols, t_cols, cnt_s, cnt_t, e);
    dinv_kernel<<<cdiv(n, 256), 256>>>(cnt_s, cnt_t, dv_s, dv_t, n);
    scan1_kernel<<<dim3(SCAN_NBLK, 2), 1024>>>(cnt_s, start_s, cnt_t, start_t, bsum, n);
    scan2_kernel<<<2, 128>>>(bsum);
    scan3_kernel<<<dim3(cdiv(n, 256), 2), 256>>>(start_s, cur_s, start_t, cur_t, bsum, n);
    place_kernel<<<eg, 256>>>(s_rows, s_cols, t_rows, t_cols, dv_s, dv_t,
                              cur_s, cur_t, adj_s, adj_t, e);

    // ---- layer 1 (spatial) ----
    xw1_kernel<<<ng16, 256>>>(x, w1, xw, n);
    gather_kernel<<<ng16, 256>>>(adj_s, start_s, cnt_s, dv_s, xw, b1, agg, n);
    bn_stats_kernel<<<512, 256>>>(agg, n);
    bn_finalize_kernel<<<1, 64>>>(g1, be1, n);

    // ---- layer 2 (spatial) ----
    xw_fused_kernel<<<cdiv(n, 64), 128>>>(agg, w2, xw, n);
    gather_kernel<<<ng16, 256>>>(adj_s, start_s, cnt_s, dv_s, xw, b2, agg, n);
    bn_stats_kernel<<<512, 256>>>(agg, n);
    bn_finalize_kernel<<<1, 64>>>(g2, be2, n);

    // ---- layer 3 (temporal) ----
    xw_fused_kernel<<<cdiv(n, 64), 128>>>(agg, w3, xw, n);
    gather_kernel<<<ng16, 256>>>(adj_t, start_t, cnt_t, dv_t, xw, b3, agg, n);
    bn_stats_kernel<<<512, 256>>>(agg, n);
    bn_finalize_kernel<<<1, 64>>>(g3, be3, n);

    // ---- layer 4 (temporal) ----
    xw_fused_kernel<<<cdiv(n, 64), 128>>>(agg, w4, xw, n);
    gather_kernel<<<ng16, 256>>>(adj_t, start_t, cnt_t, dv_t, xw, b4, agg, n);
    bn_stats_kernel<<<512, 256>>>(agg, n);
    bn_finalize_kernel<<<1, 64>>>(g4, be4, n);

    // ---- final FC ----
    fc_kernel<<<cdiv(n, 128), 128>>>(agg, wfc, bfc, out, n);
}

// round 9
// speedup vs baseline: 1.0708x; 1.0708x over previous
#include <cuda_runtime.h>
#include <cuda_fp16.h>
#include <cstdint>

#define NN 100000
#define NE 1600000
#define HD 64
#define IND 5
#define OUTD 4
#define BN_EPS 1e-5f
#define TS 65   // padded tile row stride (floats)
#define SCAN_NBLK 98   // cdiv(100000, 1024)

// ---------------- scratch (static; no allocation allowed) ----------------
__device__ __half g_xwh[(size_t)NN * HD];        // fp16 projected features
__device__ float  g_agg[(size_t)NN * HD];
__device__ int    g_cnt_s[NN], g_cnt_t[NN];
__device__ int    g_start_s[NN], g_start_t[NN];
__device__ int    g_cur_s[NN],  g_cur_t[NN];
__device__ float  g_dv_s[NN],  g_dv_t[NN];
__device__ int2   g_adj_s[NE], g_adj_t[NE];      // (row, norm-bits), grouped by col
__device__ int    g_bsum[256];                   // [2][128] block sums for scan
__device__ double g_sum[HD], g_sumsq[HD];
__device__ float  g_a[HD], g_c[HD];              // BN scale/shift

static inline int cdiv(long long a, int b) { return (int)((a + b - 1) / b); }

// fp16x4 (uint2) -> fp32 fma into float4 accumulator
__device__ __forceinline__ void fma_h4(float4& acc, uint2 r, float w) {
    __half2 h0 = *reinterpret_cast<__half2*>(&r.x);
    __half2 h1 = *reinterpret_cast<__half2*>(&r.y);
    float2 f0 = __half22float2(h0);
    float2 f1 = __half22float2(h1);
    acc.x = fmaf(w, f0.x, acc.x);
    acc.y = fmaf(w, f0.y, acc.y);
    acc.z = fmaf(w, f1.x, acc.z);
    acc.w = fmaf(w, f1.y, acc.w);
}

// ---------------- CSR build ----------------
__global__ void zero_cnt_kernel(int* a, int* b, int n) {
    int i = blockIdx.x * blockDim.x + threadIdx.x;
    if (i < n) { a[i] = 0; b[i] = 0; }
}

__global__ void count_kernel(const int* __restrict__ s_cols, const int* __restrict__ t_cols,
                             int* __restrict__ cnt_s, int* __restrict__ cnt_t, int nE) {
    int e = blockIdx.x * blockDim.x + threadIdx.x;
    if (e < nE) {
        atomicAdd(&cnt_s[s_cols[e]], 1);
        atomicAdd(&cnt_t[t_cols[e]], 1);
    }
}

__global__ void dinv_kernel(const int* __restrict__ ca, const int* __restrict__ cb,
                            float* __restrict__ da, float* __restrict__ db, int n) {
    int i = blockIdx.x * blockDim.x + threadIdx.x;
    if (i < n) {
        da[i] = rsqrtf((float)ca[i] + 1.0f);
        db[i] = rsqrtf((float)cb[i] + 1.0f);
    }
}

// ---- parallel 3-phase exclusive scan ----
__global__ void scan1_kernel(const int* __restrict__ cnt_s, int* __restrict__ start_s,
                             const int* __restrict__ cnt_t, int* __restrict__ start_t,
                             int* __restrict__ bsum, int n) {
    const int* cnt = blockIdx.y ? cnt_t : cnt_s;
    int* start = blockIdx.y ? start_t : start_s;
    __shared__ int sh[1024];
    int t = threadIdx.x;
    int i = blockIdx.x * 1024 + t;
    int v = (i < n) ? cnt[i] : 0;
    sh[t] = v;
    __syncthreads();
    #pragma unroll
    for (int off = 1; off < 1024; off <<= 1) {
        int x = (t >= off) ? sh[t - off] : 0;
        __syncthreads();
        sh[t] += x;
        __syncthreads();
    }
    if (i < n) start[i] = sh[t] - v;
    if (t == 1023) bsum[blockIdx.y * 128 + blockIdx.x] = sh[1023];
}

__global__ void scan2_kernel(int* __restrict__ bsum) {
    int* bs = bsum + blockIdx.x * 128;
    __shared__ int sh[128];
    int t = threadIdx.x;
    int v = (t < SCAN_NBLK) ? bs[t] : 0;
    sh[t] = v;
    __syncthreads();
    #pragma unroll
    for (int off = 1; off < 128; off <<= 1) {
        int x = (t >= off) ? sh[t - off] : 0;
        __syncthreads();
        sh[t] += x;
        __syncthreads();
    }
    bs[t] = sh[t] - v;
}

__global__ void scan3_kernel(int* __restrict__ start_s, int* __restrict__ cur_s,
                             int* __restrict__ start_t, int* __restrict__ cur_t,
                             const int* __restrict__ bsum, int n) {
    int g = blockIdx.y;
    int* start = g ? start_t : start_s;
    int* cur   = g ? cur_t   : cur_s;
    int i = blockIdx.x * blockDim.x + threadIdx.x;
    if (i < n) {
        int v = start[i] + bsum[g * 128 + (i >> 10)];
        start[i] = v;
        cur[i] = v;
    }
}

__global__ void place_kernel(const int* __restrict__ s_rows, const int* __restrict__ s_cols,
                             const int* __restrict__ t_rows, const int* __restrict__ t_cols,
                             const float* __restrict__ dv_s, const float* __restrict__ dv_t,
                             int* __restrict__ cur_s, int* __restrict__ cur_t,
                             int2* __restrict__ adj_s, int2* __restrict__ adj_t, int nE) {
    int e = blockIdx.x * blockDim.x + threadIdx.x;
    if (e >= nE) return;
    {
        int r = s_rows[e], c = s_cols[e];
        int pos = atomicAdd(&cur_s[c], 1);
        adj_s[pos] = make_int2(r, __float_as_int(dv_s[r] * dv_s[c]));
    }
    {
        int r = t_rows[e], c = t_cols[e];
        int pos = atomicAdd(&cur_t[c], 1);
        adj_t[pos] = make_int2(r, __float_as_int(dv_t[r] * dv_t[c]));
    }
}

// ---------------- layer 1 projection: xw = x(Nx5) @ w1(5x64), fp16 out ----------------
__global__ void xw1_kernel(const float* __restrict__ x, const float* __restrict__ w,
                           __half* __restrict__ outh, int n) {
    __shared__ float Ws[IND * HD];
    int t = threadIdx.x;
    for (int i = t; i < IND * HD; i += blockDim.x) Ws[i] = w[i];
    __syncthreads();
    int idx = blockIdx.x * blockDim.x + t;
    int node = idx >> 4, q = idx & 15;
    if (node >= n) return;
    float xr[IND];
    #pragma unroll
    for (int k = 0; k < IND; k++) xr[k] = __ldg(&x[(size_t)node * IND + k]);
    float4 a = make_float4(0.f, 0.f, 0.f, 0.f);
    #pragma unroll
    for (int k = 0; k < IND; k++) {
        const float* wr = &Ws[k * HD + q * 4];
        a.x = fmaf(xr[k], wr[0], a.x);
        a.y = fmaf(xr[k], wr[1], a.y);
        a.z = fmaf(xr[k], wr[2], a.z);
        a.w = fmaf(xr[k], wr[3], a.w);
    }
    __half2 h0 = __floats2half2_rn(a.x, a.y);
    __half2 h1 = __floats2half2_rn(a.z, a.w);
    uint2 o;
    o.x = *reinterpret_cast<unsigned*>(&h0);
    o.y = *reinterpret_cast<unsigned*>(&h1);
    ((uint2*)outh)[(size_t)node * 16 + q] = o;
}

// ---------------- aggregation (gather over CSR), fp16 inputs ----------------
// agg[c] = b + dinv[c]^2 * xw[c] + sum_{edges into c} norm * xw[row]
// 16 lanes per node; unroll-4 batched loads. fp32 accumulation.
__global__ void __launch_bounds__(256)
gather_kernel(const int2* __restrict__ adj, const int* __restrict__ start,
              const int* __restrict__ cnt, const float* __restrict__ dinv,
              const __half* __restrict__ xwh, const float* __restrict__ bias,
              float* __restrict__ agg, int n) {
    int t = threadIdx.x;
    if (blockIdx.x == 0 && t < HD) { g_sum[t] = 0.0; g_sumsq[t] = 0.0; }
    int idx = blockIdx.x * 256 + t;
    int node = idx >> 4, q = idx & 15;
    if (node >= n) return;

    const uint2* xw2 = (const uint2*)xwh;
    float4 acc = __ldg(&((const float4*)bias)[q]);
    float s = dinv[node]; s *= s;
    uint2 selfr = __ldg(&xw2[(size_t)node * 16 + q]);
    fma_h4(acc, selfr, s);

    int p  = start[node];
    int p1 = p + cnt[node];
    for (; p + 4 <= p1; p += 4) {
        int2 a0 = __ldg(&adj[p]);
        int2 a1 = __ldg(&adj[p + 1]);
        int2 a2 = __ldg(&adj[p + 2]);
        int2 a3 = __ldg(&adj[p + 3]);
        uint2 r0 = __ldg(&xw2[(size_t)a0.x * 16 + q]);
        uint2 r1 = __ldg(&xw2[(size_t)a1.x * 16 + q]);
        uint2 r2 = __ldg(&xw2[(size_t)a2.x * 16 + q]);
        uint2 r3 = __ldg(&xw2[(size_t)a3.x * 16 + q]);
        fma_h4(acc, r0, __int_as_float(a0.y));
        fma_h4(acc, r1, __int_as_float(a1.y));
        fma_h4(acc, r2, __int_as_float(a2.y));
        fma_h4(acc, r3, __int_as_float(a3.y));
    }
    for (; p < p1; p++) {
        int2 a = __ldg(&adj[p]);
        uint2 r = __ldg(&xw2[(size_t)a.x * 16 + q]);
        fma_h4(acc, r, __int_as_float(a.y));
    }
    ((float4*)agg)[(size_t)node * 16 + q] = acc;
}

// ---------------- BN stats: column sums / sumsq ----------------
__global__ void bn_stats_kernel(const float* __restrict__ agg, int n) {
    int t = threadIdx.x;              // 256
    int col = t & 63, sub = t >> 6;
    float s = 0.f, s2 = 0.f;
    for (int i = blockIdx.x * 4 + sub; i < n; i += gridDim.x * 4) {
        float v = agg[(size_t)i * HD + col];
        s += v;
        s2 = fmaf(v, v, s2);
    }
    __shared__ float sh0[256], sh1[256];
    sh0[t] = s; sh1[t] = s2;
    __syncthreads();
    if (sub == 0) {
        double ds  = (double)sh0[t] + sh0[t + 64] + sh0[t + 128] + sh0[t + 192];
        double ds2 = (double)sh1[t] + sh1[t + 64] + sh1[t + 128] + sh1[t + 192];
        atomicAdd(&g_sum[col], ds);
        atomicAdd(&g_sumsq[col], ds2);
    }
}

__global__ void bn_finalize_kernel(const float* __restrict__ g, const float* __restrict__ be, int n) {
    int t = threadIdx.x;
    if (t >= HD) return;
    double mean = g_sum[t] / n;
    double var  = g_sumsq[t] / n - mean * mean;
    float a = g[t] * rsqrtf((float)var + BN_EPS);
    g_a[t] = a;
    g_c[t] = be[t] - (float)mean * a;
}

// ---------------- fused BN+ReLU+GEMM: xw = relu(bn(agg)) @ W, fp16 out ----------------
// block = 128 threads = 64 nodes, 2 threads per node (32 outputs each).
__global__ void __launch_bounds__(128)
xw_fused_kernel(const float* __restrict__ in, const float* __restrict__ W,
                __half* __restrict__ outh, int n) {
    __shared__ float tile[64 * TS];
    __shared__ float Ws[HD * HD];
    __shared__ float as[HD], cs[HD];
    int t = threadIdx.x;
    for (int i = t; i < HD * HD; i += 128) Ws[i] = W[i];
    if (t < HD) { as[t] = g_a[t]; cs[t] = g_c[t]; }

    int base = blockIdx.x * 64;
    int nv = min(64, n - base);
    const float4* in4 = (const float4*)(in + (size_t)base * HD);
    for (int i = t; i < nv * 16; i += 128) {
        float4 v = __ldg(&in4[i]);
        float* p = &tile[(i >> 4) * TS + (i & 15) * 4];
        p[0] = v.x; p[1] = v.y; p[2] = v.z; p[3] = v.w;
    }
    __syncthreads();

    int node = t >> 1, h = t & 1;
    if ((base + node) >= n) return;
    float acc[32];
    #pragma unroll
    for (int j = 0; j < 32; j++) acc[j] = 0.f;
    {
        const float* row = &tile[node * TS];
        const float* wb  = &Ws[h * 32];
        #pragma unroll 4
        for (int k = 0; k < HD; k++) {
            float v = fmaxf(fmaf(row[k], as[k], cs[k]), 0.f);
            #pragma unroll
            for (int j = 0; j < 32; j++) acc[j] = fmaf(v, wb[k * HD + j], acc[j]);
        }
    }
    // direct fp16 store: this thread owns 32 contiguous cols = 64 B
    unsigned packed[16];
    #pragma unroll
    for (int j = 0; j < 16; j++) {
        __half2 hv = __floats2half2_rn(acc[2 * j], acc[2 * j + 1]);
        packed[j] = *reinterpret_cast<unsigned*>(&hv);
    }
    uint4* dst = (uint4*)(outh + (size_t)(base + node) * HD + h * 32);
    #pragma unroll
    for (int j = 0; j < 4; j++)
        dst[j] = make_uint4(packed[4*j], packed[4*j+1], packed[4*j+2], packed[4*j+3]);
}

// ---------------- final FC: out = relu(bn(agg)) @ wfc + bfc ----------------
__global__ void __launch_bounds__(128)
fc_kernel(const float* __restrict__ agg, const float* __restrict__ wfc,
          const float* __restrict__ bfc, float* __restrict__ out, int n) {
    __shared__ float tile[128 * TS];
    __shared__ float Wf[HD * OUTD];
    __shared__ float as[HD], cs[HD];
    int t = threadIdx.x;
    if (t < HD) { as[t] = g_a[t]; cs[t] = g_c[t]; }
    if (t < HD) ((float4*)Wf)[t] = ((const float4*)wfc)[t];

    int base = blockIdx.x * 128;
    int nv = min(128, n - base);
    const float4* in4 = (const float4*)(agg + (size_t)base * HD);
    for (int i = t; i < nv * 16; i += 128) {
        float4 v = __ldg(&in4[i]);
        float* p = &tile[(i >> 4) * TS + (i & 15) * 4];
        p[0] = v.x; p[1] = v.y; p[2] = v.z; p[3] = v.w;
    }
    __syncthreads();
    if (t < nv) {
        float a0 = __ldg(&bfc[0]), a1 = __ldg(&bfc[1]);
        float a2 = __ldg(&bfc[2]), a3 = __ldg(&bfc[3]);
        const float* row = &tile[t * TS];
        #pragma unroll 8
        for (int k = 0; k < HD; k++) {
            float v = fmaxf(fmaf(row[k], as[k], cs[k]), 0.f);
            a0 = fmaf(v, Wf[k * 4 + 0], a0);
            a1 = fmaf(v, Wf[k * 4 + 1], a1);
            a2 = fmaf(v, Wf[k * 4 + 2], a2);
            a3 = fmaf(v, Wf[k * 4 + 3], a3);
        }
        ((float4*)out)[base + t] = make_float4(a0, a1, a2, a3);
    }
}

// ---------------- host orchestration ----------------
extern "C" void kernel_launch(void* const* d_in, const int* in_sizes, int n_in,
                              void* d_out, int out_size) {
    const float* x   = (const float*)d_in[0];
    const int*   sei = (const int*)d_in[1];
    const int*   tei = (const int*)d_in[2];
    const float* w1  = (const float*)d_in[3];
    const float* b1  = (const float*)d_in[4];
    const float* g1  = (const float*)d_in[5];
    const float* be1 = (const float*)d_in[6];
    const float* w2  = (const float*)d_in[7];
    const float* b2  = (const float*)d_in[8];
    const float* g2  = (const float*)d_in[9];
    const float* be2 = (const float*)d_in[10];
    const float* w3  = (const float*)d_in[11];
    const float* b3  = (const float*)d_in[12];
    const float* g3  = (const float*)d_in[13];
    const float* be3 = (const float*)d_in[14];
    const float* w4  = (const float*)d_in[15];
    const float* b4  = (const float*)d_in[16];
    const float* g4  = (const float*)d_in[17];
    const float* be4 = (const float*)d_in[18];
    const float* wfc = (const float*)d_in[19];
    const float* bfc = (const float*)d_in[20];
    float* out = (float*)d_out;

    const int n = in_sizes[0] / IND;   // 100000
    const int e = in_sizes[1] / 2;     // 1600000
    const int* s_rows = sei;  const int* s_cols = sei + e;
    const int* t_rows = tei;  const int* t_cols = tei + e;

    int *cnt_s, *cnt_t, *start_s, *start_t, *cur_s, *cur_t, *bsum;
    float *dv_s, *dv_t, *agg;
    __half* xwh;
    int2 *adj_s, *adj_t;
    cudaGetSymbolAddress((void**)&cnt_s, g_cnt_s);
    cudaGetSymbolAddress((void**)&cnt_t, g_cnt_t);
    cudaGetSymbolAddress((void**)&start_s, g_start_s);
    cudaGetSymbolAddress((void**)&start_t, g_start_t);
    cudaGetSymbolAddress((void**)&cur_s, g_cur_s);
    cudaGetSymbolAddress((void**)&cur_t, g_cur_t);
    cudaGetSymbolAddress((void**)&dv_s, g_dv_s);
    cudaGetSymbolAddress((void**)&dv_t, g_dv_t);
    cudaGetSymbolAddress((void**)&xwh, g_xwh);
    cudaGetSymbolAddress((void**)&agg, g_agg);
    cudaGetSymbolAddress((void**)&adj_s, g_adj_s);
    cudaGetSymbolAddress((void**)&adj_t, g_adj_t);
    cudaGetSymbolAddress((void**)&bsum, g_bsum);

    const int eg = cdiv(e, 256);
    const int ng16 = cdiv((long long)n * 16, 256);

    // ---- CSR build (once per graph, reused by 2 layers each) ----
    zero_cnt_kernel<<<cdiv(n, 256), 256>>>(cnt_s, cnt_t, n);
    count_kernel<<<eg, 256>>>(s_cols, t_cols, cnt_s, cnt_t, e);
    dinv_kernel<<<cdiv(n, 256), 256>>>(cnt_s, cnt_t, dv_s, dv_t, n);
    scan1_kernel<<<dim3(SCAN_NBLK, 2), 1024>>>(cnt_s, start_s, cnt_t, start_t, bsum, n);
    scan2_kernel<<<2, 128>>>(bsum);
    scan3_kernel<<<dim3(cdiv(n, 256), 2), 256>>>(start_s, cur_s, start_t, cur_t, bsum, n);
    place_kernel<<<eg, 256>>>(s_rows, s_cols, t_rows, t_cols, dv_s, dv_t,
                              cur_s, cur_t, adj_s, adj_t, e);

    // ---- layer 1 (spatial) ----
    xw1_kernel<<<ng16, 256>>>(x, w1, xwh, n);
    gather_kernel<<<ng16, 256>>>(adj_s, start_s, cnt_s, dv_s, xwh, b1, agg, n);
    bn_stats_kernel<<<512, 256>>>(agg, n);
    bn_finalize_kernel<<<1, 64>>>(g1, be1, n);

    // ---- layer 2 (spatial) ----
    xw_fused_kernel<<<cdiv(n, 64), 128>>>(agg, w2, xwh, n);
    gather_kernel<<<ng16, 256>>>(adj_s, start_s, cnt_s, dv_s, xwh, b2, agg, n);
    bn_stats_kernel<<<512, 256>>>(agg, n);
    bn_finalize_kernel<<<1, 64>>>(g2, be2, n);

    // ---- layer 3 (temporal) ----
    xw_fused_kernel<<<cdiv(n, 64), 128>>>(agg, w3, xwh, n);
    gather_kernel<<<ng16, 256>>>(adj_t, start_t, cnt_t, dv_t, xwh, b3, agg, n);
    bn_stats_kernel<<<512, 256>>>(agg, n);
    bn_finalize_kernel<<<1, 64>>>(g3, be3, n);

    // ---- layer 4 (temporal) ----
    xw_fused_kernel<<<cdiv(n, 64), 128>>>(agg, w4, xwh, n);
    gather_kernel<<<ng16, 256>>>(adj_t, start_t, cnt_t, dv_t, xwh, b4, agg, n);
    bn_stats_kernel<<<512, 256>>>(agg, n);
    bn_finalize_kernel<<<1, 64>>>(g4, be4, n);

    // ---- final FC ----
    fc_kernel<<<cdiv(n, 128), 128>>>(agg, wfc, bfc, out, n);
}

// round 10
// speedup vs baseline: 1.0980x; 1.0254x over previous
#include <cuda_runtime.h>
#include <cuda_fp16.h>
#include <cstdint>

#define NN 100000
#define NE 1600000
#define HD 64
#define IND 5
#define OUTD 4
#define BN_EPS 1e-5f
#define TS 65   // padded tile row stride (floats)
#define SCAN_NBLK 98   // cdiv(100000, 1024)
#define GC 4           // gather chunk (edges per cp.async group)

// ---------------- scratch (static; no allocation allowed) ----------------
__device__ __align__(16) __half g_xwh[(size_t)NN * HD];   // fp16 projected features
__device__ float  g_agg[(size_t)NN * HD];
__device__ int    g_cnt_s[NN], g_cnt_t[NN];
__device__ int    g_start_s[NN], g_start_t[NN];
__device__ int    g_cur_s[NN],  g_cur_t[NN];
__device__ float  g_dv_s[NN],  g_dv_t[NN];
__device__ int2   g_adj_s[NE], g_adj_t[NE];      // (row, norm-bits), grouped by col
__device__ int    g_bsum[256];                   // [2][128] raw block sums for scan
__device__ double g_sum[HD], g_sumsq[HD];

static inline int cdiv(long long a, int b) { return (int)((a + b - 1) / b); }

// 8 fp16 (uint4) -> fp32 fma into acc[8]
__device__ __forceinline__ void fma_h8(float* acc, uint4 v, float w) {
    __half2 h; float2 f;
    h = *reinterpret_cast<__half2*>(&v.x); f = __half22float2(h);
    acc[0] = fmaf(w, f.x, acc[0]); acc[1] = fmaf(w, f.y, acc[1]);
    h = *reinterpret_cast<__half2*>(&v.y); f = __half22float2(h);
    acc[2] = fmaf(w, f.x, acc[2]); acc[3] = fmaf(w, f.y, acc[3]);
    h = *reinterpret_cast<__half2*>(&v.z); f = __half22float2(h);
    acc[4] = fmaf(w, f.x, acc[4]); acc[5] = fmaf(w, f.y, acc[5]);
    h = *reinterpret_cast<__half2*>(&v.w); f = __half22float2(h);
    acc[6] = fmaf(w, f.x, acc[6]); acc[7] = fmaf(w, f.y, acc[7]);
}

// ---------------- CSR build ----------------
// both graphs in one pass (cnt arrays are pre-zeroed: static init on first
// call, fc_kernel epilogue on every call)
__global__ void count_kernel(const int* __restrict__ s_cols, const int* __restrict__ t_cols,
                             int* __restrict__ cnt_s, int* __restrict__ cnt_t, int nE) {
    int e = blockIdx.x * blockDim.x + threadIdx.x;
    if (e < nE) {
        atomicAdd(&cnt_s[s_cols[e]], 1);
        atomicAdd(&cnt_t[t_cols[e]], 1);
    }
}

// per-block scan of counts + dinv computation; gridDim = (SCAN_NBLK, 2)
__global__ void scan1_kernel(const int* __restrict__ cnt_s, int* __restrict__ start_s,
                             const int* __restrict__ cnt_t, int* __restrict__ start_t,
                             float* __restrict__ dv_s, float* __restrict__ dv_t,
                             int* __restrict__ bsum, int n) {
    const int* cnt = blockIdx.y ? cnt_t : cnt_s;
    int* start = blockIdx.y ? start_t : start_s;
    float* dv = blockIdx.y ? dv_t : dv_s;
    __shared__ int sh[1024];
    int t = threadIdx.x;
    int i = blockIdx.x * 1024 + t;
    int v = (i < n) ? cnt[i] : 0;
    if (i < n) dv[i] = rsqrtf((float)v + 1.0f);
    sh[t] = v;
    __syncthreads();
    #pragma unroll
    for (int off = 1; off < 1024; off <<= 1) {
        int x = (t >= off) ? sh[t - off] : 0;
        __syncthreads();
        sh[t] += x;
        __syncthreads();
    }
    if (i < n) start[i] = sh[t] - v;   // exclusive within block
    if (t == 1023) bsum[blockIdx.y * 128 + blockIdx.x] = sh[1023];
}

// combined block-offset computation + apply; gridDim = (cdiv(n,256), 2)
__global__ void scan23_kernel(int* __restrict__ start_s, int* __restrict__ cur_s,
                              int* __restrict__ start_t, int* __restrict__ cur_t,
                              const int* __restrict__ bsum, int n) {
    int g = blockIdx.y;
    int* start = g ? start_t : start_s;
    int* cur   = g ? cur_t   : cur_s;
    int t = threadIdx.x;
    int bi = blockIdx.x >> 2;   // 1024-element chunk index of this 256-block
    __shared__ int sh[128];
    if (t < 128) sh[t] = (t < bi) ? bsum[g * 128 + t] : 0;
    __syncthreads();
    #pragma unroll
    for (int off = 64; off > 0; off >>= 1) {
        if (t < off) sh[t] += sh[t + off];
        __syncthreads();
    }
    int offset = sh[0];
    int i = blockIdx.x * 256 + t;
    if (i < n) {
        int val = start[i] + offset;
        start[i] = val;
        cur[i] = val;
    }
}

// both graphs in one pass
__global__ void place_kernel(const int* __restrict__ s_rows, const int* __restrict__ s_cols,
                             const int* __restrict__ t_rows, const int* __restrict__ t_cols,
                             const float* __restrict__ dv_s, const float* __restrict__ dv_t,
                             int* __restrict__ cur_s, int* __restrict__ cur_t,
                             int2* __restrict__ adj_s, int2* __restrict__ adj_t, int nE) {
    int e = blockIdx.x * blockDim.x + threadIdx.x;
    if (e >= nE) return;
    {
        int r = s_rows[e], c = s_cols[e];
        int pos = atomicAdd(&cur_s[c], 1);
        adj_s[pos] = make_int2(r, __float_as_int(dv_s[r] * dv_s[c]));
    }
    {
        int r = t_rows[e], c = t_cols[e];
        int pos = atomicAdd(&cur_t[c], 1);
        adj_t[pos] = make_int2(r, __float_as_int(dv_t[r] * dv_t[c]));
    }
}

// ---------------- layer 1 projection: xw = x(Nx5) @ w1(5x64), fp16 out ----------------
__global__ void xw1_kernel(const float* __restrict__ x, const float* __restrict__ w,
                           __half* __restrict__ outh, int n) {
    __shared__ float Ws[IND * HD];
    int t = threadIdx.x;
    for (int i = t; i < IND * HD; i += blockDim.x) Ws[i] = w[i];
    __syncthreads();
    int idx = blockIdx.x * blockDim.x + t;
    int node = idx >> 4, q = idx & 15;
    if (node >= n) return;
    float xr[IND];
    #pragma unroll
    for (int k = 0; k < IND; k++) xr[k] = __ldg(&x[(size_t)node * IND + k]);
    float4 a = make_float4(0.f, 0.f, 0.f, 0.f);
    #pragma unroll
    for (int k = 0; k < IND; k++) {
        const float* wr = &Ws[k * HD + q * 4];
        a.x = fmaf(xr[k], wr[0], a.x);
        a.y = fmaf(xr[k], wr[1], a.y);
        a.z = fmaf(xr[k], wr[2], a.z);
        a.w = fmaf(xr[k], wr[3], a.w);
    }
    __half2 h0 = __floats2half2_rn(a.x, a.y);
    __half2 h1 = __floats2half2_rn(a.z, a.w);
    uint2 o;
    o.x = *reinterpret_cast<unsigned*>(&h0);
    o.y = *reinterpret_cast<unsigned*>(&h1);
    ((uint2*)outh)[(size_t)node * 16 + q] = o;
}

// ---------------- aggregation: cp.async.cg staged gather over CSR ----------------
// agg[c] = b + dinv[c]^2 * xw[c] + sum_{edges into c} norm * xw[row]
// 8 lanes/node, 16 B per lane. Edge rows staged through smem with
// cp.async.cg (L1 bypass, untracked by LSU scoreboard) in 4-edge
// double-buffered chunks. Summation order identical to the R9 loop.
__global__ void __launch_bounds__(256)
gather_kernel(const int2* __restrict__ adj, const int* __restrict__ start,
              const int* __restrict__ cnt, const float* __restrict__ dinv,
              const __half* __restrict__ xwh, const float* __restrict__ bias,
              float* __restrict__ agg, int n) {
    __shared__ __align__(16) uint4 stage[2][GC][256];
    int t = threadIdx.x;
    if (blockIdx.x == 0 && t < HD) { g_sum[t] = 0.0; g_sumsq[t] = 0.0; }
    int idx = blockIdx.x * 256 + t;
    int node = idx >> 3, q = idx & 7;
    if (node >= n) return;

    const uint4* xw4 = (const uint4*)xwh;
    float acc[8];
    {
        float4 b0 = __ldg(&((const float4*)bias)[q * 2]);
        float4 b1 = __ldg(&((const float4*)bias)[q * 2 + 1]);
        acc[0] = b0.x; acc[1] = b0.y; acc[2] = b0.z; acc[3] = b0.w;
        acc[4] = b1.x; acc[5] = b1.y; acc[6] = b1.z; acc[7] = b1.w;
    }
    float s = dinv[node]; s *= s;
    fma_h8(acc, __ldg(&xw4[(size_t)node * 8 + q]), s);

    int p  = start[node];
    int p1 = p + cnt[node];

    uint32_t sm0 = (uint32_t)__cvta_generic_to_shared(&stage[0][0][t]);
    uint32_t sm1 = (uint32_t)__cvta_generic_to_shared(&stage[1][0][t]);
    const uint32_t jstride = 256u * 16u;

    float n0[GC], n1[GC];
    int c0 = 0, c1 = 0;

#define G_ISSUE(smbase, narr, cvar) do {                                        \
    cvar = min(GC, p1 - p);                                                     \
    _Pragma("unroll")                                                           \
    for (int j = 0; j < GC; j++) {                                              \
        if (j < cvar) {                                                         \
            int2 a = __ldg(&adj[p + j]);                                        \
            narr[j] = __int_as_float(a.y);                                      \
            const uint4* src = &xw4[(size_t)a.x * 8 + q];                       \
            asm volatile("cp.async.cg.shared.global [%0], [%1], 16;"            \
                         :: "r"(smbase + j * jstride), "l"(src));               \
        }                                                                       \
    }                                                                           \
    asm volatile("cp.async.commit_group;");                                     \
    p += cvar;                                                                  \
} while (0)

#define G_CONSUME(sidx, narr, cvar) do {                                        \
    _Pragma("unroll")                                                           \
    for (int j = 0; j < GC; j++) {                                              \
        if (j < cvar) fma_h8(acc, stage[sidx][j][t], narr[j]);                  \
    }                                                                           \
} while (0)

    G_ISSUE(sm0, n0, c0);
    while (p < p1) {
        G_ISSUE(sm1, n1, c1);
        asm volatile("cp.async.wait_group 1;" ::: "memory");
        G_CONSUME(0, n0, c0);
        if (p < p1) {
            G_ISSUE(sm0, n0, c0);
            asm volatile("cp.async.wait_group 1;" ::: "memory");
            G_CONSUME(1, n1, c1);
        } else {
            asm volatile("cp.async.wait_group 0;" ::: "memory");
            G_CONSUME(1, n1, c1);
            c0 = 0;
            break;
        }
    }
    asm volatile("cp.async.wait_group 0;" ::: "memory");
    G_CONSUME(0, n0, c0);
#undef G_ISSUE
#undef G_CONSUME

    float4* dst = (float4*)(agg + (size_t)node * HD + q * 8);
    dst[0] = make_float4(acc[0], acc[1], acc[2], acc[3]);
    dst[1] = make_float4(acc[4], acc[5], acc[6], acc[7]);
}

// ---------------- BN stats: column sums / sumsq ----------------
__global__ void bn_stats_kernel(const float* __restrict__ agg, int n) {
    int t = threadIdx.x;              // 256
    int col = t & 63, sub = t >> 6;
    float s = 0.f, s2 = 0.f;
    for (int i = blockIdx.x * 4 + sub; i < n; i += gridDim.x * 4) {
        float v = agg[(size_t)i * HD + col];
        s += v;
        s2 = fmaf(v, v, s2);
    }
    __shared__ float sh0[256], sh1[256];
    sh0[t] = s; sh1[t] = s2;
    __syncthreads();
    if (sub == 0) {
        double ds  = (double)sh0[t] + sh0[t + 64] + sh0[t + 128] + sh0[t + 192];
        double ds2 = (double)sh1[t] + sh1[t + 64] + sh1[t + 128] + sh1[t + 192];
        atomicAdd(&g_sum[col], ds);
        atomicAdd(&g_sumsq[col], ds2);
    }
}

// ---------------- fused BN-finalize+BN+ReLU+GEMM: xw = relu(bn(agg)) @ W, fp16 out ----
// Each block redundantly computes the BN scale/shift from the global stat
// accumulators (identical math to the former bn_finalize kernel).
__global__ void __launch_bounds__(128)
xw_fused_kernel(const float* __restrict__ in, const float* __restrict__ W,
                const float* __restrict__ gg, const float* __restrict__ be,
                __half* __restrict__ outh, int n) {
    __shared__ float tile[64 * TS];
    __shared__ float Ws[HD * HD];
    __shared__ float as[HD], cs[HD];
    int t = threadIdx.x;
    for (int i = t; i < HD * HD; i += 128) Ws[i] = W[i];
    if (t < HD) {
        double mean = g_sum[t] / n;
        double var  = g_sumsq[t] / n - mean * mean;
        float a = gg[t] * rsqrtf((float)var + BN_EPS);
        as[t] = a;
        cs[t] = be[t] - (float)mean * a;
    }

    int base = blockIdx.x * 64;
    int nv = min(64, n - base);
    const float4* in4 = (const float4*)(in + (size_t)base * HD);
    for (int i = t; i < nv * 16; i += 128) {
        float4 v = __ldg(&in4[i]);
        float* p = &tile[(i >> 4) * TS + (i & 15) * 4];
        p[0] = v.x; p[1] = v.y; p[2] = v.z; p[3] = v.w;
    }
    __syncthreads();

    int node = t >> 1, h = t & 1;
    if ((base + node) >= n) return;
    float acc[32];
    #pragma unroll
    for (int j = 0; j < 32; j++) acc[j] = 0.f;
    {
        const float* row = &tile[node * TS];
        const float* wb  = &Ws[h * 32];
        #pragma unroll 4
        for (int k = 0; k < HD; k++) {
            float v = fmaxf(fmaf(row[k], as[k], cs[k]), 0.f);
            #pragma unroll
            for (int j = 0; j < 32; j++) acc[j] = fmaf(v, wb[k * HD + j], acc[j]);
        }
    }
    unsigned packed[16];
    #pragma unroll
    for (int j = 0; j < 16; j++) {
        __half2 hv = __floats2half2_rn(acc[2 * j], acc[2 * j + 1]);
        packed[j] = *reinterpret_cast<unsigned*>(&hv);
    }
    uint4* dst = (uint4*)(outh + (size_t)(base + node) * HD + h * 32);
    #pragma unroll
    for (int j = 0; j < 4; j++)
        dst[j] = make_uint4(packed[4*j], packed[4*j+1], packed[4*j+2], packed[4*j+3]);
}

// ---------------- final FC (+BN finalize, + cnt re-zero for next call) ----------------
__global__ void __launch_bounds__(128)
fc_kernel(const float* __restrict__ agg, const float* __restrict__ wfc,
          const float* __restrict__ bfc, const float* __restrict__ gg,
          const float* __restrict__ be, float* __restrict__ out, int n) {
    __shared__ float tile[128 * TS];
    __shared__ float Wf[HD * OUTD];
    __shared__ float as[HD], cs[HD];
    int t = threadIdx.x;
    if (t < HD) {
        double mean = g_sum[t] / n;
        double var  = g_sumsq[t] / n - mean * mean;
        float a = gg[t] * rsqrtf((float)var + BN_EPS);
        as[t] = a;
        cs[t] = be[t] - (float)mean * a;
        ((float4*)Wf)[t] = ((const float4*)wfc)[t];
    }

    int base = blockIdx.x * 128;
    // re-zero degree counters for the next kernel_launch invocation
    {
        int i = base + t;
        if (i < n) { g_cnt_s[i] = 0; g_cnt_t[i] = 0; }
    }
    int nv = min(128, n - base);
    const float4* in4 = (const float4*)(agg + (size_t)base * HD);
    for (int i = t; i < nv * 16; i += 128) {
        float4 v = __ldg(&in4[i]);
        float* p = &tile[(i >> 4) * TS + (i & 15) * 4];
        p[0] = v.x; p[1] = v.y; p[2] = v.z; p[3] = v.w;
    }
    __syncthreads();
    if (t < nv) {
        float a0 = __ldg(&bfc[0]), a1 = __ldg(&bfc[1]);
        float a2 = __ldg(&bfc[2]), a3 = __ldg(&bfc[3]);
        const float* row = &tile[t * TS];
        #pragma unroll 8
        for (int k = 0; k < HD; k++) {
            float v = fmaxf(fmaf(row[k], as[k], cs[k]), 0.f);
            a0 = fmaf(v, Wf[k * 4 + 0], a0);
            a1 = fmaf(v, Wf[k * 4 + 1], a1);
            a2 = fmaf(v, Wf[k * 4 + 2], a2);
            a3 = fmaf(v, Wf[k * 4 + 3], a3);
        }
        ((float4*)out)[base + t] = make_float4(a0, a1, a2, a3);
    }
}

// ---------------- host orchestration ----------------
extern "C" void kernel_launch(void* const* d_in, const int* in_sizes, int n_in,
                              void* d_out, int out_size) {
    const float* x   = (const float*)d_in[0];
    const int*   sei = (const int*)d_in[1];
    const int*   tei = (const int*)d_in[2];
    const float* w1  = (const float*)d_in[3];
    const float* b1  = (const float*)d_in[4];
    const float* g1  = (const float*)d_in[5];
    const float* be1 = (const float*)d_in[6];
    const float* w2  = (const float*)d_in[7];
    const float* b2  = (const float*)d_in[8];
    const float* g2  = (const float*)d_in[9];
    const float* be2 = (const float*)d_in[10];
    const float* w3  = (const float*)d_in[11];
    const float* b3  = (const float*)d_in[12];
    const float* g3  = (const float*)d_in[13];
    const float* be3 = (const float*)d_in[14];
    const float* w4  = (const float*)d_in[15];
    const float* b4  = (const float*)d_in[16];
    const float* g4  = (const float*)d_in[17];
    const float* be4 = (const float*)d_in[18];
    const float* wfc = (const float*)d_in[19];
    const float* bfc = (const float*)d_in[20];
    float* out = (float*)d_out;

    const int n = in_sizes[0] / IND;   // 100000
    const int e = in_sizes[1] / 2;     // 1600000
    const int* s_rows = sei;  const int* s_cols = sei + e;
    const int* t_rows = tei;  const int* t_cols = tei + e;

    int *cnt_s, *cnt_t, *start_s, *start_t, *cur_s, *cur_t, *bsum;
    float *dv_s, *dv_t, *agg;
    __half* xwh;
    int2 *adj_s, *adj_t;
    cudaGetSymbolAddress((void**)&cnt_s, g_cnt_s);
    cudaGetSymbolAddress((void**)&cnt_t, g_cnt_t);
    cudaGetSymbolAddress((void**)&start_s, g_start_s);
    cudaGetSymbolAddress((void**)&start_t, g_start_t);
    cudaGetSymbolAddress((void**)&cur_s, g_cur_s);
    cudaGetSymbolAddress((void**)&cur_t, g_cur_t);
    cudaGetSymbolAddress((void**)&dv_s, g_dv_s);
    cudaGetSymbolAddress((void**)&dv_t, g_dv_t);
    cudaGetSymbolAddress((void**)&xwh, g_xwh);
    cudaGetSymbolAddress((void**)&agg, g_agg);
    cudaGetSymbolAddress((void**)&adj_s, g_adj_s);
    cudaGetSymbolAddress((void**)&adj_t, g_adj_t);
    cudaGetSymbolAddress((void**)&bsum, g_bsum);

    const int eg   = cdiv(e, 256);
    const int ng16 = cdiv((long long)n * 16, 256);
    const int ng8  = cdiv((long long)n * 8, 256);

    // ---- CSR build (cnt pre-zeroed by previous call's fc / static init) ----
    count_kernel<<<eg, 256>>>(s_cols, t_cols, cnt_s, cnt_t, e);
    scan1_kernel<<<dim3(SCAN_NBLK, 2), 1024>>>(cnt_s, start_s, cnt_t, start_t,
                                               dv_s, dv_t, bsum, n);
    scan23_kernel<<<dim3(cdiv(n, 256), 2), 256>>>(start_s, cur_s, start_t, cur_t, bsum, n);
    place_kernel<<<eg, 256>>>(s_rows, s_cols, t_rows, t_cols, dv_s, dv_t,
                              cur_s, cur_t, adj_s, adj_t, e);

    // ---- layer 1 (spatial) ----
    xw1_kernel<<<ng16, 256>>>(x, w1, xwh, n);
    gather_kernel<<<ng8, 256>>>(adj_s, start_s, cnt_s, dv_s, xwh, b1, agg, n);
    bn_stats_kernel<<<512, 256>>>(agg, n);

    // ---- layer 2 (spatial) ----
    xw_fused_kernel<<<cdiv(n, 64), 128>>>(agg, w2, g1, be1, xwh, n);
    gather_kernel<<<ng8, 256>>>(adj_s, start_s, cnt_s, dv_s, xwh, b2, agg, n);
    bn_stats_kernel<<<512, 256>>>(agg, n);

    // ---- layer 3 (temporal) ----
    xw_fused_kernel<<<cdiv(n, 64), 128>>>(agg, w3, g2, be2, xwh, n);
    gather_kernel<<<ng8, 256>>>(adj_t, start_t, cnt_t, dv_t, xwh, b3, agg, n);
    bn_stats_kernel<<<512, 256>>>(agg, n);

    // ---- layer 4 (temporal) ----
    xw_fused_kernel<<<cdiv(n, 64), 128>>>(agg, w4, g3, be3, xwh, n);
    gather_kernel<<<ng8, 256>>>(adj_t, start_t, cnt_t, dv_t, xwh, b4, agg, n);
    bn_stats_kernel<<<512, 256>>>(agg, n);

    // ---- final FC (+BN finalize of layer 4, + cnt re-zero) ----
    fc_kernel<<<cdiv(n, 128), 128>>>(agg, wfc, bfc, g4, be4, out, n);
}

// round 11
// speedup vs baseline: 1.1796x; 1.0744x over previous
#include <cuda_runtime.h>
#include <cuda_fp16.h>
#include <cstdint>

#define NN 100000
#define NE 1600000
#define HD 64
#define IND 5
#define OUTD 4
#define BN_EPS 1e-5f
#define TS 65   // padded tile row stride (floats)
#define SCAN_NBLK 98   // cdiv(100000, 1024)

// ---------------- scratch (static; no allocation allowed) ----------------
__device__ __align__(16) __half g_xwh[(size_t)NN * HD];   // fp16 dv-prescaled features
__device__ float  g_agg[(size_t)NN * HD];
__device__ int    g_cnt_s[NN], g_cnt_t[NN];
__device__ int    g_start_s[NN], g_start_t[NN];
__device__ int    g_cur_s[NN],  g_cur_t[NN];
__device__ float  g_dv_s[NN],  g_dv_t[NN];
__device__ int    g_adj_s[NE], g_adj_t[NE];      // row index per edge, grouped by col
__device__ int    g_bsum[256];                   // [2][128] raw block sums for scan
__device__ double g_sum[HD], g_sumsq[HD];

static inline int cdiv(long long a, int b) { return (int)((a + b - 1) / b); }

// 8 fp16 (uint4) -> fp32 add into acc[8]
__device__ __forceinline__ void add_h8(float* acc, uint4 v) {
    __half2 h; float2 f;
    h = *reinterpret_cast<__half2*>(&v.x); f = __half22float2(h);
    acc[0] += f.x; acc[1] += f.y;
    h = *reinterpret_cast<__half2*>(&v.y); f = __half22float2(h);
    acc[2] += f.x; acc[3] += f.y;
    h = *reinterpret_cast<__half2*>(&v.z); f = __half22float2(h);
    acc[4] += f.x; acc[5] += f.y;
    h = *reinterpret_cast<__half2*>(&v.w); f = __half22float2(h);
    acc[6] += f.x; acc[7] += f.y;
}

// ---------------- CSR build ----------------
// cnt arrays pre-zeroed (static init first call; fc_kernel epilogue after)
__global__ void count_kernel(const int* __restrict__ s_cols, const int* __restrict__ t_cols,
                             int* __restrict__ cnt_s, int* __restrict__ cnt_t, int nE) {
    int e = blockIdx.x * blockDim.x + threadIdx.x;
    if (e < nE) {
        atomicAdd(&cnt_s[s_cols[e]], 1);
        atomicAdd(&cnt_t[t_cols[e]], 1);
    }
}

// per-block scan of counts + dinv; gridDim = (SCAN_NBLK, 2)
__global__ void scan1_kernel(const int* __restrict__ cnt_s, int* __restrict__ start_s,
                             const int* __restrict__ cnt_t, int* __restrict__ start_t,
                             float* __restrict__ dv_s, float* __restrict__ dv_t,
                             int* __restrict__ bsum, int n) {
    const int* cnt = blockIdx.y ? cnt_t : cnt_s;
    int* start = blockIdx.y ? start_t : start_s;
    float* dv = blockIdx.y ? dv_t : dv_s;
    __shared__ int sh[1024];
    int t = threadIdx.x;
    int i = blockIdx.x * 1024 + t;
    int v = (i < n) ? cnt[i] : 0;
    if (i < n) dv[i] = rsqrtf((float)v + 1.0f);
    sh[t] = v;
    __syncthreads();
    #pragma unroll
    for (int off = 1; off < 1024; off <<= 1) {
        int x = (t >= off) ? sh[t - off] : 0;
        __syncthreads();
        sh[t] += x;
        __syncthreads();
    }
    if (i < n) start[i] = sh[t] - v;   // exclusive within block
    if (t == 1023) bsum[blockIdx.y * 128 + blockIdx.x] = sh[1023];
}

// combined block-offset computation + apply; gridDim = (cdiv(n,256), 2)
__global__ void scan23_kernel(int* __restrict__ start_s, int* __restrict__ cur_s,
                              int* __restrict__ start_t, int* __restrict__ cur_t,
                              const int* __restrict__ bsum, int n) {
    int g = blockIdx.y;
    int* start = g ? start_t : start_s;
    int* cur   = g ? cur_t   : cur_s;
    int t = threadIdx.x;
    int bi = blockIdx.x >> 2;   // 1024-element chunk index of this 256-block
    __shared__ int sh[128];
    if (t < 128) sh[t] = (t < bi) ? bsum[g * 128 + t] : 0;
    __syncthreads();
    #pragma unroll
    for (int off = 64; off > 0; off >>= 1) {
        if (t < off) sh[t] += sh[t + off];
        __syncthreads();
    }
    int offset = sh[0];
    int i = blockIdx.x * 256 + t;
    if (i < n) {
        int val = start[i] + offset;
        start[i] = val;
        cur[i] = val;
    }
}

// both graphs in one pass; scatter only the row index (4 B), no dv reads
__global__ void place_kernel(const int* __restrict__ s_rows, const int* __restrict__ s_cols,
                             const int* __restrict__ t_rows, const int* __restrict__ t_cols,
                             int* __restrict__ cur_s, int* __restrict__ cur_t,
                             int* __restrict__ adj_s, int* __restrict__ adj_t, int nE) {
    int e = blockIdx.x * blockDim.x + threadIdx.x;
    if (e >= nE) return;
    {
        int pos = atomicAdd(&cur_s[s_cols[e]], 1);
        adj_s[pos] = s_rows[e];
    }
    {
        int pos = atomicAdd(&cur_t[t_cols[e]], 1);
        adj_t[pos] = t_rows[e];
    }
}

// ---------------- layer 1 projection: xs = dv .* (x @ w1), fp16 out ----------------
__global__ void xw1_kernel(const float* __restrict__ x, const float* __restrict__ w,
                           const float* __restrict__ dv, __half* __restrict__ outh, int n) {
    __shared__ float Ws[IND * HD];
    int t = threadIdx.x;
    for (int i = t; i < IND * HD; i += blockDim.x) Ws[i] = w[i];
    __syncthreads();
    int idx = blockIdx.x * blockDim.x + t;
    int node = idx >> 4, q = idx & 15;
    if (node >= n) return;
    float xr[IND];
    #pragma unroll
    for (int k = 0; k < IND; k++) xr[k] = __ldg(&x[(size_t)node * IND + k]);
    float4 a = make_float4(0.f, 0.f, 0.f, 0.f);
    #pragma unroll
    for (int k = 0; k < IND; k++) {
        const float* wr = &Ws[k * HD + q * 4];
        a.x = fmaf(xr[k], wr[0], a.x);
        a.y = fmaf(xr[k], wr[1], a.y);
        a.z = fmaf(xr[k], wr[2], a.z);
        a.w = fmaf(xr[k], wr[3], a.w);
    }
    float d = __ldg(&dv[node]);
    __half2 h0 = __floats2half2_rn(d * a.x, d * a.y);
    __half2 h1 = __floats2half2_rn(d * a.z, d * a.w);
    uint2 o;
    o.x = *reinterpret_cast<unsigned*>(&h0);
    o.y = *reinterpret_cast<unsigned*>(&h1);
    ((uint2*)outh)[(size_t)node * 16 + q] = o;
}

// ---------------- aggregation (gather over CSR, weightless) ----------------
// agg[c] = b + dv[c] * ( sum_{edges into c} xs[row] + xs[c] )
// 8 lanes per node (16 B each); unroll-4 batched loads; fp32 accumulation.
__global__ void __launch_bounds__(256)
gather_kernel(const int* __restrict__ adj, const int* __restrict__ start,
              const int* __restrict__ cnt, const float* __restrict__ dinv,
              const __half* __restrict__ xwh, const float* __restrict__ bias,
              float* __restrict__ agg, int n) {
    int t = threadIdx.x;
    if (blockIdx.x == 0 && t < HD) { g_sum[t] = 0.0; g_sumsq[t] = 0.0; }
    int idx = blockIdx.x * 256 + t;
    int node = idx >> 3, q = idx & 7;
    if (node >= n) return;

    const uint4* xw4 = (const uint4*)xwh;
    float acc[8];
    {
        uint4 selfv = __ldg(&xw4[(size_t)node * 8 + q]);
        __half2 h; float2 f;
        h = *reinterpret_cast<__half2*>(&selfv.x); f = __half22float2(h);
        acc[0] = f.x; acc[1] = f.y;
        h = *reinterpret_cast<__half2*>(&selfv.y); f = __half22float2(h);
        acc[2] = f.x; acc[3] = f.y;
        h = *reinterpret_cast<__half2*>(&selfv.z); f = __half22float2(h);
        acc[4] = f.x; acc[5] = f.y;
        h = *reinterpret_cast<__half2*>(&selfv.w); f = __half22float2(h);
        acc[6] = f.x; acc[7] = f.y;
    }

    int p  = start[node];
    int p1 = p + cnt[node];
    for (; p + 4 <= p1; p += 4) {
        int r0 = __ldg(&adj[p]);
        int r1 = __ldg(&adj[p + 1]);
        int r2 = __ldg(&adj[p + 2]);
        int r3 = __ldg(&adj[p + 3]);
        uint4 v0 = __ldg(&xw4[(size_t)r0 * 8 + q]);
        uint4 v1 = __ldg(&xw4[(size_t)r1 * 8 + q]);
        uint4 v2 = __ldg(&xw4[(size_t)r2 * 8 + q]);
        uint4 v3 = __ldg(&xw4[(size_t)r3 * 8 + q]);
        add_h8(acc, v0);
        add_h8(acc, v1);
        add_h8(acc, v2);
        add_h8(acc, v3);
    }
    for (; p < p1; p++) {
        int r = __ldg(&adj[p]);
        add_h8(acc, __ldg(&xw4[(size_t)r * 8 + q]));
    }

    float d = __ldg(&dinv[node]);
    float4 b0 = __ldg(&((const float4*)bias)[q * 2]);
    float4 b1 = __ldg(&((const float4*)bias)[q * 2 + 1]);
    float4* dst = (float4*)(agg + (size_t)node * HD + q * 8);
    dst[0] = make_float4(fmaf(d, acc[0], b0.x), fmaf(d, acc[1], b0.y),
                         fmaf(d, acc[2], b0.z), fmaf(d, acc[3], b0.w));
    dst[1] = make_float4(fmaf(d, acc[4], b1.x), fmaf(d, acc[5], b1.y),
                         fmaf(d, acc[6], b1.z), fmaf(d, acc[7], b1.w));
}

// ---------------- BN stats: column sums / sumsq ----------------
__global__ void bn_stats_kernel(const float* __restrict__ agg, int n) {
    int t = threadIdx.x;              // 256
    int col = t & 63, sub = t >> 6;
    float s = 0.f, s2 = 0.f;
    for (int i = blockIdx.x * 4 + sub; i < n; i += gridDim.x * 4) {
        float v = agg[(size_t)i * HD + col];
        s += v;
        s2 = fmaf(v, v, s2);
    }
    __shared__ float sh0[256], sh1[256];
    sh0[t] = s; sh1[t] = s2;
    __syncthreads();
    if (sub == 0) {
        double ds  = (double)sh0[t] + sh0[t + 64] + sh0[t + 128] + sh0[t + 192];
        double ds2 = (double)sh1[t] + sh1[t + 64] + sh1[t + 128] + sh1[t + 192];
        atomicAdd(&g_sum[col], ds);
        atomicAdd(&g_sumsq[col], ds2);
    }
}

// ---------------- fused BN-finalize+BN+ReLU+GEMM, dv-prescaled fp16 out ----------------
// Each block redundantly computes BN scale/shift from global stat accumulators.
__global__ void __launch_bounds__(128)
xw_fused_kernel(const float* __restrict__ in, const float* __restrict__ W,
                const float* __restrict__ gg, const float* __restrict__ be,
                const float* __restrict__ dv, __half* __restrict__ outh, int n) {
    __shared__ float tile[64 * TS];
    __shared__ float Ws[HD * HD];
    __shared__ float as[HD], cs[HD];
    int t = threadIdx.x;
    for (int i = t; i < HD * HD; i += 128) Ws[i] = W[i];
    if (t < HD) {
        double mean = g_sum[t] / n;
        double var  = g_sumsq[t] / n - mean * mean;
        float a = gg[t] * rsqrtf((float)var + BN_EPS);
        as[t] = a;
        cs[t] = be[t] - (float)mean * a;
    }

    int base = blockIdx.x * 64;
    int nv = min(64, n - base);
    const float4* in4 = (const float4*)(in + (size_t)base * HD);
    for (int i = t; i < nv * 16; i += 128) {
        float4 v = __ldg(&in4[i]);
        float* p = &tile[(i >> 4) * TS + (i & 15) * 4];
        p[0] = v.x; p[1] = v.y; p[2] = v.z; p[3] = v.w;
    }
    __syncthreads();

    int node = t >> 1, h = t & 1;
    if ((base + node) >= n) return;
    float acc[32];
    #pragma unroll
    for (int j = 0; j < 32; j++) acc[j] = 0.f;
    {
        const float* row = &tile[node * TS];
        const float* wb  = &Ws[h * 32];
        #pragma unroll 4
        for (int k = 0; k < HD; k++) {
            float v = fmaxf(fmaf(row[k], as[k], cs[k]), 0.f);
            #pragma unroll
            for (int j = 0; j < 32; j++) acc[j] = fmaf(v, wb[k * HD + j], acc[j]);
        }
    }
    float d = __ldg(&dv[base + node]);
    unsigned packed[16];
    #pragma unroll
    for (int j = 0; j < 16; j++) {
        __half2 hv = __floats2half2_rn(d * acc[2 * j], d * acc[2 * j + 1]);
        packed[j] = *reinterpret_cast<unsigned*>(&hv);
    }
    uint4* dst = (uint4*)(outh + (size_t)(base + node) * HD + h * 32);
    #pragma unroll
    for (int j = 0; j < 4; j++)
        dst[j] = make_uint4(packed[4*j], packed[4*j+1], packed[4*j+2], packed[4*j+3]);
}

// ---------------- final FC (+BN finalize, + cnt re-zero for next call) ----------------
__global__ void __launch_bounds__(128)
fc_kernel(const float* __restrict__ agg, const float* __restrict__ wfc,
          const float* __restrict__ bfc, const float* __restrict__ gg,
          const float* __restrict__ be, float* __restrict__ out, int n) {
    __shared__ float tile[128 * TS];
    __shared__ float Wf[HD * OUTD];
    __shared__ float as[HD], cs[HD];
    int t = threadIdx.x;
    if (t < HD) {
        double mean = g_sum[t] / n;
        double var  = g_sumsq[t] / n - mean * mean;
        float a = gg[t] * rsqrtf((float)var + BN_EPS);
        as[t] = a;
        cs[t] = be[t] - (float)mean * a;
        ((float4*)Wf)[t] = ((const float4*)wfc)[t];
    }

    int base = blockIdx.x * 128;
    // re-zero degree counters for the next kernel_launch invocation
    {
        int i = base + t;
        if (i < n) { g_cnt_s[i] = 0; g_cnt_t[i] = 0; }
    }
    int nv = min(128, n - base);
    const float4* in4 = (const float4*)(agg + (size_t)base * HD);
    for (int i = t; i < nv * 16; i += 128) {
        float4 v = __ldg(&in4[i]);
        float* p = &tile[(i >> 4) * TS + (i & 15) * 4];
        p[0] = v.x; p[1] = v.y; p[2] = v.z; p[3] = v.w;
    }
    __syncthreads();
    if (t < nv) {
        float a0 = __ldg(&bfc[0]), a1 = __ldg(&bfc[1]);
        float a2 = __ldg(&bfc[2]), a3 = __ldg(&bfc[3]);
        const float* row = &tile[t * TS];
        #pragma unroll 8
        for (int k = 0; k < HD; k++) {
            float v = fmaxf(fmaf(row[k], as[k], cs[k]), 0.f);
            a0 = fmaf(v, Wf[k * 4 + 0], a0);
            a1 = fmaf(v, Wf[k * 4 + 1], a1);
            a2 = fmaf(v, Wf[k * 4 + 2], a2);
            a3 = fmaf(v, Wf[k * 4 + 3], a3);
        }
        ((float4*)out)[base + t] = make_float4(a0, a1, a2, a3);
    }
}

// ---------------- host orchestration ----------------
extern "C" void kernel_launch(void* const* d_in, const int* in_sizes, int n_in,
                              void* d_out, int out_size) {
    const float* x   = (const float*)d_in[0];
    const int*   sei = (const int*)d_in[1];
    const int*   tei = (const int*)d_in[2];
    const float* w1  = (const float*)d_in[3];
    const float* b1  = (const float*)d_in[4];
    const float* g1  = (const float*)d_in[5];
    const float* be1 = (const float*)d_in[6];
    const float* w2  = (const float*)d_in[7];
    const float* b2  = (const float*)d_in[8];
    const float* g2  = (const float*)d_in[9];
    const float* be2 = (const float*)d_in[10];
    const float* w3  = (const float*)d_in[11];
    const float* b3  = (const float*)d_in[12];
    const float* g3  = (const float*)d_in[13];
    const float* be3 = (const float*)d_in[14];
    const float* w4  = (const float*)d_in[15];
    const float* b4  = (const float*)d_in[16];
    const float* g4  = (const float*)d_in[17];
    const float* be4 = (const float*)d_in[18];
    const float* wfc = (const float*)d_in[19];
    const float* bfc = (const float*)d_in[20];
    float* out = (float*)d_out;

    const int n = in_sizes[0] / IND;   // 100000
    const int e = in_sizes[1] / 2;     // 1600000
    const int* s_rows = sei;  const int* s_cols = sei + e;
    const int* t_rows = tei;  const int* t_cols = tei + e;

    int *cnt_s, *cnt_t, *start_s, *start_t, *cur_s, *cur_t, *bsum;
    float *dv_s, *dv_t, *agg;
    __half* xwh;
    int *adj_s, *adj_t;
    cudaGetSymbolAddress((void**)&cnt_s, g_cnt_s);
    cudaGetSymbolAddress((void**)&cnt_t, g_cnt_t);
    cudaGetSymbolAddress((void**)&start_s, g_start_s);
    cudaGetSymbolAddress((void**)&start_t, g_start_t);
    cudaGetSymbolAddress((void**)&cur_s, g_cur_s);
    cudaGetSymbolAddress((void**)&cur_t, g_cur_t);
    cudaGetSymbolAddress((void**)&dv_s, g_dv_s);
    cudaGetSymbolAddress((void**)&dv_t, g_dv_t);
    cudaGetSymbolAddress((void**)&xwh, g_xwh);
    cudaGetSymbolAddress((void**)&agg, g_agg);
    cudaGetSymbolAddress((void**)&adj_s, g_adj_s);
    cudaGetSymbolAddress((void**)&adj_t, g_adj_t);
    cudaGetSymbolAddress((void**)&bsum, g_bsum);

    const int eg   = cdiv(e, 256);
    const int ng16 = cdiv((long long)n * 16, 256);
    const int ng8  = cdiv((long long)n * 8, 256);

    // ---- CSR build (cnt pre-zeroed by previous call's fc / static init) ----
    count_kernel<<<eg, 256>>>(s_cols, t_cols, cnt_s, cnt_t, e);
    scan1_kernel<<<dim3(SCAN_NBLK, 2), 1024>>>(cnt_s, start_s, cnt_t, start_t,
                                               dv_s, dv_t, bsum, n);
    scan23_kernel<<<dim3(cdiv(n, 256), 2), 256>>>(start_s, cur_s, start_t, cur_t, bsum, n);
    place_kernel<<<eg, 256>>>(s_rows, s_cols, t_rows, t_cols,
                              cur_s, cur_t, adj_s, adj_t, e);

    // ---- layer 1 (spatial) ----
    xw1_kernel<<<ng16, 256>>>(x, w1, dv_s, xwh, n);
    gather_kernel<<<ng8, 256>>>(adj_s, start_s, cnt_s, dv_s, xwh, b1, agg, n);
    bn_stats_kernel<<<512, 256>>>(agg, n);

    // ---- layer 2 (spatial) ----
    xw_fused_kernel<<<cdiv(n, 64), 128>>>(agg, w2, g1, be1, dv_s, xwh, n);
    gather_kernel<<<ng8, 256>>>(adj_s, start_s, cnt_s, dv_s, xwh, b2, agg, n);
    bn_stats_kernel<<<512, 256>>>(agg, n);

    // ---- layer 3 (temporal) ----
    xw_fused_kernel<<<cdiv(n, 64), 128>>>(agg, w3, g2, be2, dv_t, xwh, n);
    gather_kernel<<<ng8, 256>>>(adj_t, start_t, cnt_t, dv_t, xwh, b3, agg, n);
    bn_stats_kernel<<<512, 256>>>(agg, n);

    // ---- layer 4 (temporal) ----
    xw_fused_kernel<<<cdiv(n, 64), 128>>>(agg, w4, g3, be3, dv_t, xwh, n);
    gather_kernel<<<ng8, 256>>>(adj_t, start_t, cnt_t, dv_t, xwh, b4, agg, n);
    bn_stats_kernel<<<512, 256>>>(agg, n);

    // ---- final FC (+BN finalize of layer 4, + cnt re-zero) ----
    fc_kernel<<<cdiv(n, 128), 128>>>(agg, wfc, bfc, g4, be4, out, n);
}